// round 6
// baseline (speedup 1.0000x reference)
#include <cuda_runtime.h>
#include <cstdint>
#include <cstddef>

// Split-K scratch. bcast folds the K-reduction: E = E1+E2, D = D1+D2 (bias in D1).
__device__ float g_E1[2048 * 1024];
__device__ float g_E2[2048 * 1024];
__device__ float g_D1[512 * 1024];
__device__ float g_D2[512 * 1024];

constexpr int KDIM = 512, NDIM = 1024;
constexpr int BM = 128, BN = 128, BK = 32;
constexpr int KSPLIT = 2;
constexpr int NKT_L = KDIM / KSPLIT / BK;   // 8 k-tiles per CTA
constexpr int STR = 136;                    // bank-conflict-free smem stride
constexpr int ASZ = BK * STR;               // words per tile buffer
constexpr int SMEM_BYTES = 4 * ASZ * 4;     // As[2] + Bs[2] = 69632 B (dynamic)

__device__ __forceinline__ uint32_t f2tf32(float x) {
    uint32_t r;
    asm("cvt.rna.tf32.f32 %0, %1;" : "=r"(r) : "f"(x));
    return r;
}

__device__ __forceinline__ void mma_tf32(float* c, const uint32_t* a, const uint32_t* b) {
    asm volatile(
        "mma.sync.aligned.m16n8k8.row.col.f32.tf32.tf32.f32 "
        "{%0,%1,%2,%3}, {%4,%5,%6,%7}, {%8,%9}, {%0,%1,%2,%3};\n"
        : "+f"(c[0]), "+f"(c[1]), "+f"(c[2]), "+f"(c[3])
        : "r"(a[0]), "r"(a[1]), "r"(a[2]), "r"(a[3]), "r"(b[0]), "r"(b[1]));
}

// ---------------------------------------------------------------------------
// tf32 NT GEMM, split-K x2, E and D fused in one launch.
// grid = (8, 40): y<32 -> E tiles (16 row-tiles x 2 ksplits), else D (4 x 2).
// Block 128x128, 8 warps (2x4), warp tile 64x32, mma m16n8k8.
// Double-buffered smem, ONE barrier per k-tile.
// ---------------------------------------------------------------------------
__global__ void __launch_bounds__(256)
gemm_tf32(const float* __restrict__ enc, const float* __restrict__ dec,
          const float* __restrict__ W, const float* __restrict__ bias)
{
    extern __shared__ uint32_t su[];

    const int tid  = threadIdx.x;
    const int col0 = blockIdx.x * BN;
    const int y    = blockIdx.y;
    const bool isE = (y < 32);
    int ti, ksl;
    const float* A;
    float* C;
    if (isE) { ti = y >> 1;  ksl = y & 1;  A = enc; C = ksl ? g_E2 : g_E1; }
    else     { int z = y - 32; ti = z >> 1; ksl = z & 1; A = dec; C = ksl ? g_D2 : g_D1; }
    const int row0 = ti * BM;
    const int k0   = ksl * (KDIM / KSPLIT);

    // Staging: 2 threads per row, each covers 16 consecutive k
    const int arow = tid >> 1;
    const int kh   = (tid & 1) * 16;
    const float* aptr = A + (size_t)(row0 + arow) * KDIM + k0 + kh;
    const float* bptr = W + (size_t)(col0 + arow) * KDIM + k0 + kh;

    const int lane = tid & 31, warp = tid >> 5;
    const int g = lane >> 2, tig = lane & 3;
    const int wm = (warp >> 2) * 64, wn = (warp & 3) * 32;

    float acc[4][4][4] = {};

    float4 pa[4], pb[4];
#pragma unroll
    for (int j = 0; j < 4; j++) {
        pa[j] = *(const float4*)(aptr + j * 4);
        pb[j] = *(const float4*)(bptr + j * 4);
    }
    {   // stage tile 0 into buffer 0
        uint32_t* As = su;
        uint32_t* Bs = su + 2 * ASZ;
#pragma unroll
        for (int j = 0; j < 4; j++) {
            As[(kh + j * 4 + 0) * STR + arow] = f2tf32(pa[j].x);
            As[(kh + j * 4 + 1) * STR + arow] = f2tf32(pa[j].y);
            As[(kh + j * 4 + 2) * STR + arow] = f2tf32(pa[j].z);
            As[(kh + j * 4 + 3) * STR + arow] = f2tf32(pa[j].w);
            Bs[(kh + j * 4 + 0) * STR + arow] = f2tf32(pb[j].x);
            Bs[(kh + j * 4 + 1) * STR + arow] = f2tf32(pb[j].y);
            Bs[(kh + j * 4 + 2) * STR + arow] = f2tf32(pb[j].z);
            Bs[(kh + j * 4 + 3) * STR + arow] = f2tf32(pb[j].w);
        }
    }
    __syncthreads();

    int buf = 0;
    for (int kt = 0; kt < NKT_L; kt++) {
        const bool more = (kt + 1 < NKT_L);
        if (more) {                    // issue next global loads early
            aptr += BK; bptr += BK;
#pragma unroll
            for (int j = 0; j < 4; j++) {
                pa[j] = *(const float4*)(aptr + j * 4);
                pb[j] = *(const float4*)(bptr + j * 4);
            }
        }

        const uint32_t* As = su + buf * ASZ;
        const uint32_t* Bs = su + 2 * ASZ + buf * ASZ;
#pragma unroll
        for (int ks = 0; ks < 4; ks++) {
            const int k8 = ks * 8;
            uint32_t af[4][4], bf[4][2];
#pragma unroll
            for (int mf = 0; mf < 4; mf++) {
                const int m = wm + mf * 16 + g;
                af[mf][0] = As[(k8 + tig) * STR + m];
                af[mf][1] = As[(k8 + tig) * STR + m + 8];
                af[mf][2] = As[(k8 + tig + 4) * STR + m];
                af[mf][3] = As[(k8 + tig + 4) * STR + m + 8];
            }
#pragma unroll
            for (int nf = 0; nf < 4; nf++) {
                const int n = wn + nf * 8 + g;
                bf[nf][0] = Bs[(k8 + tig) * STR + n];
                bf[nf][1] = Bs[(k8 + tig + 4) * STR + n];
            }
#pragma unroll
            for (int mf = 0; mf < 4; mf++)
#pragma unroll
                for (int nf = 0; nf < 4; nf++)
                    mma_tf32(acc[mf][nf], af[mf], bf[nf]);
        }

        if (more) {                    // stage next tile into the other buffer
            uint32_t* Asn = su + (buf ^ 1) * ASZ;
            uint32_t* Bsn = su + 2 * ASZ + (buf ^ 1) * ASZ;
#pragma unroll
            for (int j = 0; j < 4; j++) {
                Asn[(kh + j * 4 + 0) * STR + arow] = f2tf32(pa[j].x);
                Asn[(kh + j * 4 + 1) * STR + arow] = f2tf32(pa[j].y);
                Asn[(kh + j * 4 + 2) * STR + arow] = f2tf32(pa[j].z);
                Asn[(kh + j * 4 + 3) * STR + arow] = f2tf32(pa[j].w);
                Bsn[(kh + j * 4 + 0) * STR + arow] = f2tf32(pb[j].x);
                Bsn[(kh + j * 4 + 1) * STR + arow] = f2tf32(pb[j].y);
                Bsn[(kh + j * 4 + 2) * STR + arow] = f2tf32(pb[j].z);
                Bsn[(kh + j * 4 + 3) * STR + arow] = f2tf32(pb[j].w);
            }
        }
        __syncthreads();
        buf ^= 1;
    }

    // epilogue (+ bias only on the D / ksplit-0 part)
    const bool addb = (!isE) && (ksl == 0);
    float2 bv[4];
#pragma unroll
    for (int nf = 0; nf < 4; nf++) {
        if (addb) bv[nf] = *(const float2*)(bias + col0 + wn + nf * 8 + tig * 2);
        else      bv[nf] = make_float2(0.f, 0.f);
    }
#pragma unroll
    for (int mf = 0; mf < 4; mf++) {
        const int r = row0 + wm + mf * 16 + g;
#pragma unroll
        for (int nf = 0; nf < 4; nf++) {
            const int c = col0 + wn + nf * 8 + tig * 2;
            float2 v0 = make_float2(acc[mf][nf][0] + bv[nf].x,
                                    acc[mf][nf][1] + bv[nf].y);
            float2 v1 = make_float2(acc[mf][nf][2] + bv[nf].x,
                                    acc[mf][nf][3] + bv[nf].y);
            *(float2*)(C + (size_t)r * NDIM + c)       = v0;
            *(float2*)(C + (size_t)(r + 8) * NDIM + c) = v1;
        }
    }
}

// ---------------------------------------------------------------------------
// Broadcast add with folded split-K reduction:
// out[b,t,u,v] = (E1+E2)[b*256+t, v] + (D1+D2)[b*64+u, v]
// 256 blocks x 256 threads, 8 t-rows per block, u unrolled x2 for load MLP,
// streaming stores (output is write-once; keep D tables L2-resident).
// ---------------------------------------------------------------------------
constexpr int TT = 8;

__global__ void __launch_bounds__(256)
bcast_add(float* __restrict__ out)
{
    const int tile = blockIdx.x;        // 0..255
    const int b    = tile >> 5;         // 0..7
    const int t0   = (tile & 31) * TT;
    const int v4   = threadIdx.x;

    const float4* E1 = (const float4*)g_E1;
    const float4* E2 = (const float4*)g_E2;
    const float4* D1 = (const float4*)g_D1;
    const float4* D2 = (const float4*)g_D2;
    float4*       O4 = (float4*)out;

    float4 e[TT];
#pragma unroll
    for (int i = 0; i < TT; i++) {
        const size_t idx = (size_t)(b * 256 + t0 + i) * 256 + v4;
        float4 a = __ldg(E1 + idx);
        float4 c = __ldg(E2 + idx);
        e[i] = make_float4(a.x + c.x, a.y + c.y, a.z + c.z, a.w + c.w);
    }

    const size_t base = ((size_t)(b * 256 + t0) * 64) * 256 + v4;

    for (int u = 0; u < 64; u += 2) {
        const size_t r0 = (size_t)(b * 64 + u) * 256 + v4;
        float4 p0 = __ldg(D1 + r0),       q0 = __ldg(D2 + r0);
        float4 p1 = __ldg(D1 + r0 + 256), q1 = __ldg(D2 + r0 + 256);
        float4 d0 = make_float4(p0.x + q0.x, p0.y + q0.y, p0.z + q0.z, p0.w + q0.w);
        float4 d1 = make_float4(p1.x + q1.x, p1.y + q1.y, p1.z + q1.z, p1.w + q1.w);

        const size_t ou0 = base + (size_t)u * 256;
#pragma unroll
        for (int i = 0; i < TT; i++) {
            const size_t o = ou0 + (size_t)i * 64 * 256;
            __stcs(O4 + o,
                   make_float4(e[i].x + d0.x, e[i].y + d0.y, e[i].z + d0.z, e[i].w + d0.w));
            __stcs(O4 + o + 256,
                   make_float4(e[i].x + d1.x, e[i].y + d1.y, e[i].z + d1.z, e[i].w + d1.w));
        }
    }
}

// ---------------------------------------------------------------------------
extern "C" void kernel_launch(void* const* d_in, const int* in_sizes, int n_in,
                              void* d_out, int out_size) {
    const float* enc  = (const float*)d_in[0];  // (8,256,512)
    const float* dec  = (const float*)d_in[1];  // (8,64,512)
    const float* W    = (const float*)d_in[2];  // (1024,512)
    const float* bias = (const float*)d_in[3];  // (1024,)
    float* out = (float*)d_out;                 // (8,256,64,1024)

    static bool attr_done = false;
    if (!attr_done) {
        cudaFuncSetAttribute(gemm_tf32,
                             cudaFuncAttributeMaxDynamicSharedMemorySize, SMEM_BYTES);
        attr_done = true;
    }

    gemm_tf32<<<dim3(NDIM / BN, 40), 256, SMEM_BYTES>>>(enc, dec, W, bias);
    bcast_add<<<256, 256>>>(out);
}

// round 7
// speedup vs baseline: 1.3599x; 1.3599x over previous
#include <cuda_runtime.h>
#include <cstdint>
#include <cstddef>

// Scratch: E = enc@W^T (2048x1024), D = dec@W^T + bias (512x1024)
__device__ float g_E[2048 * 1024];
__device__ float g_D[512 * 1024];

constexpr int KDIM = 512, NDIM = 1024;
constexpr int BM = 128, BN = 128, BK = 32;
constexpr int NKT = KDIM / BK;        // 16 k-tiles
constexpr int STR = 136;              // padded smem row stride (bank-conflict-free)

__device__ __forceinline__ uint32_t f2tf32(float x) {
    uint32_t r;
    asm("cvt.rna.tf32.f32 %0, %1;" : "=r"(r) : "f"(x));
    return r;
}

__device__ __forceinline__ void mma_tf32(float* c, const uint32_t* a, const uint32_t* b) {
    asm volatile(
        "mma.sync.aligned.m16n8k8.row.col.f32.tf32.tf32.f32 "
        "{%0,%1,%2,%3}, {%4,%5,%6,%7}, {%8,%9}, {%0,%1,%2,%3};\n"
        : "+f"(c[0]), "+f"(c[1]), "+f"(c[2]), "+f"(c[3])
        : "r"(a[0]), "r"(a[1]), "r"(a[2]), "r"(a[3]), "r"(b[0]), "r"(b[1]));
}

// ---------------------------------------------------------------------------
// tf32 tensor-core NT GEMM producing both E and D in one launch (R3 version,
// measured ~48us). grid = (8, 20): y<16 -> E rows (enc), else D rows (dec,+bias).
// Block 128x128xK, 8 warps (2x4), warp tile 64x32, mma m16n8k8.
// ---------------------------------------------------------------------------
__global__ void __launch_bounds__(256)
gemm_tf32(const float* __restrict__ enc, const float* __restrict__ dec,
          const float* __restrict__ W, const float* __restrict__ bias,
          float* __restrict__ E, float* __restrict__ D)
{
    __shared__ uint32_t As[BK][STR];
    __shared__ uint32_t Bs[BK][STR];

    const int tid  = threadIdx.x;
    const int col0 = blockIdx.x * BN;
    const bool isE = (blockIdx.y < 16);
    const int row0 = isE ? blockIdx.y * BM : (blockIdx.y - 16) * BM;
    const float* A = isE ? enc : dec;
    float* C       = isE ? E : D;

    const int arow = tid >> 1;
    const int kh   = (tid & 1) * 16;
    const float* aptr = A + (size_t)(row0 + arow) * KDIM + kh;
    const float* bptr = W + (size_t)(col0 + arow) * KDIM + kh;

    const int lane = tid & 31, warp = tid >> 5;
    const int g = lane >> 2, tig = lane & 3;
    const int wm = (warp >> 2) * 64, wn = (warp & 3) * 32;

    float acc[4][4][4];
#pragma unroll
    for (int mf = 0; mf < 4; mf++)
#pragma unroll
        for (int nf = 0; nf < 4; nf++)
#pragma unroll
            for (int i = 0; i < 4; i++) acc[mf][nf][i] = 0.f;

    float4 pa[4], pb[4];
#pragma unroll
    for (int j = 0; j < 4; j++) {
        pa[j] = *(const float4*)(aptr + j * 4);
        pb[j] = *(const float4*)(bptr + j * 4);
    }

    for (int kt = 0; kt < NKT; kt++) {
#pragma unroll
        for (int j = 0; j < 4; j++) {
            As[kh + j * 4 + 0][arow] = f2tf32(pa[j].x);
            As[kh + j * 4 + 1][arow] = f2tf32(pa[j].y);
            As[kh + j * 4 + 2][arow] = f2tf32(pa[j].z);
            As[kh + j * 4 + 3][arow] = f2tf32(pa[j].w);
            Bs[kh + j * 4 + 0][arow] = f2tf32(pb[j].x);
            Bs[kh + j * 4 + 1][arow] = f2tf32(pb[j].y);
            Bs[kh + j * 4 + 2][arow] = f2tf32(pb[j].z);
            Bs[kh + j * 4 + 3][arow] = f2tf32(pb[j].w);
        }
        __syncthreads();

        if (kt + 1 < NKT) {
            aptr += BK; bptr += BK;
#pragma unroll
            for (int j = 0; j < 4; j++) {
                pa[j] = *(const float4*)(aptr + j * 4);
                pb[j] = *(const float4*)(bptr + j * 4);
            }
        }

#pragma unroll
        for (int ks = 0; ks < 4; ks++) {
            const int k8 = ks * 8;
            uint32_t af[4][4], bf[4][2];
#pragma unroll
            for (int mf = 0; mf < 4; mf++) {
                const int m = wm + mf * 16 + g;
                af[mf][0] = As[k8 + tig][m];
                af[mf][1] = As[k8 + tig][m + 8];
                af[mf][2] = As[k8 + tig + 4][m];
                af[mf][3] = As[k8 + tig + 4][m + 8];
            }
#pragma unroll
            for (int nf = 0; nf < 4; nf++) {
                const int n = wn + nf * 8 + g;
                bf[nf][0] = Bs[k8 + tig][n];
                bf[nf][1] = Bs[k8 + tig + 4][n];
            }
#pragma unroll
            for (int mf = 0; mf < 4; mf++)
#pragma unroll
                for (int nf = 0; nf < 4; nf++)
                    mma_tf32(acc[mf][nf], af[mf], bf[nf]);
        }
        __syncthreads();
    }

    float2 bv[4];
#pragma unroll
    for (int nf = 0; nf < 4; nf++) {
        if (isE) bv[nf] = make_float2(0.f, 0.f);
        else     bv[nf] = *(const float2*)(bias + col0 + wn + nf * 8 + tig * 2);
    }
#pragma unroll
    for (int mf = 0; mf < 4; mf++) {
        const int r = row0 + wm + mf * 16 + g;
#pragma unroll
        for (int nf = 0; nf < 4; nf++) {
            const int c = col0 + wn + nf * 8 + tig * 2;
            float2 v0 = make_float2(acc[mf][nf][0] + bv[nf].x,
                                    acc[mf][nf][1] + bv[nf].y);
            float2 v1 = make_float2(acc[mf][nf][2] + bv[nf].x,
                                    acc[mf][nf][3] + bv[nf].y);
            *(float2*)(C + (size_t)r * NDIM + c)       = v0;
            *(float2*)(C + (size_t)(r + 8) * NDIM + c) = v1;
        }
    }
}

// ---------------------------------------------------------------------------
// Broadcast add: out[b,t,u,v] = E[b*256+t, v] + D[b*64+u, v]
// TT=2 -> 1024 blocks x 256 threads (~6 CTA/SM, occ ~75%): the store stream
// needs resident warps, not fewer/bigger blocks (R6 lesson).
// u unrolled x2 for D-load MLP. Plain stores (R3's proven path).
// ---------------------------------------------------------------------------
constexpr int TT = 2;

__global__ void __launch_bounds__(256)
bcast_add(const float* __restrict__ E, const float* __restrict__ D,
          float* __restrict__ out)
{
    const int tile = blockIdx.x;            // 0..1023
    const int b    = tile >> 7;             // 0..7  (128 tiles per batch)
    const int t0   = (tile & 127) * TT;
    const int v4   = threadIdx.x;

    const float4* E4 = (const float4*)E;
    const float4* D4 = (const float4*)D;
    float4*       O4 = (float4*)out;

    float4 e0 = E4[(size_t)(b * 256 + t0 + 0) * 256 + v4];
    float4 e1 = E4[(size_t)(b * 256 + t0 + 1) * 256 + v4];

    const size_t base = ((size_t)(b * 256 + t0) * 64) * 256 + v4;
    const float4* Dp  = D4 + (size_t)(b * 64) * 256 + v4;

    for (int u = 0; u < 64; u += 2) {
        float4 d0 = __ldg(Dp + (size_t)u * 256);
        float4 d1 = __ldg(Dp + (size_t)(u + 1) * 256);

        const size_t o0 = base + (size_t)u * 256;
        O4[o0]                  = make_float4(e0.x + d0.x, e0.y + d0.y,
                                              e0.z + d0.z, e0.w + d0.w);
        O4[o0 + 256]            = make_float4(e0.x + d1.x, e0.y + d1.y,
                                              e0.z + d1.z, e0.w + d1.w);
        O4[o0 + 64 * 256]       = make_float4(e1.x + d0.x, e1.y + d0.y,
                                              e1.z + d0.z, e1.w + d0.w);
        O4[o0 + 64 * 256 + 256] = make_float4(e1.x + d1.x, e1.y + d1.y,
                                              e1.z + d1.z, e1.w + d1.w);
    }
}

// ---------------------------------------------------------------------------
extern "C" void kernel_launch(void* const* d_in, const int* in_sizes, int n_in,
                              void* d_out, int out_size) {
    const float* enc  = (const float*)d_in[0];  // (8,256,512)
    const float* dec  = (const float*)d_in[1];  // (8,64,512)
    const float* W    = (const float*)d_in[2];  // (1024,512)
    const float* bias = (const float*)d_in[3];  // (1024,)
    float* out = (float*)d_out;                 // (8,256,64,1024)

    float *E, *D;
    cudaGetSymbolAddress((void**)&E, g_E);
    cudaGetSymbolAddress((void**)&D, g_D);

    gemm_tf32<<<dim3(NDIM / BN, 20), 256>>>(enc, dec, W, bias, E, D);
    bcast_add<<<1024, 256>>>(E, D, out);
}

// round 8
// speedup vs baseline: 1.3667x; 1.0050x over previous
#include <cuda_runtime.h>
#include <cstdint>
#include <cstddef>

// Scratch: E = enc@W^T (2048x1024), D = dec@W^T + bias (512x1024)
__device__ float g_E[2048 * 1024];
__device__ float g_D[512 * 1024];

constexpr int KDIM = 512, NDIM = 1024;
constexpr int BM = 64, BN = 64, BK = 32;
constexpr int NKT = KDIM / BK;        // 16 k-tiles
constexpr int STR = 72;               // padded smem stride: (tig*8+g) stays conflict-free

__device__ __forceinline__ uint32_t f2tf32(float x) {
    uint32_t r;
    asm("cvt.rna.tf32.f32 %0, %1;" : "=r"(r) : "f"(x));
    return r;
}

__device__ __forceinline__ void mma_tf32(float* c, const uint32_t* a, const uint32_t* b) {
    asm volatile(
        "mma.sync.aligned.m16n8k8.row.col.f32.tf32.tf32.f32 "
        "{%0,%1,%2,%3}, {%4,%5,%6,%7}, {%8,%9}, {%0,%1,%2,%3};\n"
        : "+f"(c[0]), "+f"(c[1]), "+f"(c[2]), "+f"(c[3])
        : "r"(a[0]), "r"(a[1]), "r"(a[2]), "r"(a[3]), "r"(b[0]), "r"(b[1]));
}

// ---------------------------------------------------------------------------
// tf32 NT GEMM, occupancy-first retile: 64x64 CTA tile, 128 threads (4 warps
// in 2x2, warp tile 32x32, acc = 32 regs/thread -> ~5 CTAs/SM).
// grid = (16, 40): y<32 -> E row-tiles (enc), else D row-tiles (dec, +bias).
// ---------------------------------------------------------------------------
__global__ void __launch_bounds__(128)
gemm_tf32(const float* __restrict__ enc, const float* __restrict__ dec,
          const float* __restrict__ W, const float* __restrict__ bias,
          float* __restrict__ E, float* __restrict__ D)
{
    __shared__ uint32_t As[BK][STR];
    __shared__ uint32_t Bs[BK][STR];

    const int tid  = threadIdx.x;
    const int col0 = blockIdx.x * BN;
    const bool isE = (blockIdx.y < 32);
    const int row0 = isE ? blockIdx.y * BM : (blockIdx.y - 32) * BM;
    const float* A = isE ? enc : dec;
    float* C       = isE ? E : D;

    // Staging: 2 threads per row (64 rows), each covers 16 consecutive k
    const int arow = tid >> 1;
    const int kh   = (tid & 1) * 16;
    const float* aptr = A + (size_t)(row0 + arow) * KDIM + kh;
    const float* bptr = W + (size_t)(col0 + arow) * KDIM + kh;

    const int lane = tid & 31, warp = tid >> 5;
    const int g = lane >> 2, tig = lane & 3;
    const int wm = (warp >> 1) * 32, wn = (warp & 1) * 32;

    float acc[2][4][4];
#pragma unroll
    for (int mf = 0; mf < 2; mf++)
#pragma unroll
        for (int nf = 0; nf < 4; nf++)
#pragma unroll
            for (int i = 0; i < 4; i++) acc[mf][nf][i] = 0.f;

    float4 pa[4], pb[4];
#pragma unroll
    for (int j = 0; j < 4; j++) {
        pa[j] = *(const float4*)(aptr + j * 4);
        pb[j] = *(const float4*)(bptr + j * 4);
    }

    for (int kt = 0; kt < NKT; kt++) {
#pragma unroll
        for (int j = 0; j < 4; j++) {
            As[kh + j * 4 + 0][arow] = f2tf32(pa[j].x);
            As[kh + j * 4 + 1][arow] = f2tf32(pa[j].y);
            As[kh + j * 4 + 2][arow] = f2tf32(pa[j].z);
            As[kh + j * 4 + 3][arow] = f2tf32(pa[j].w);
            Bs[kh + j * 4 + 0][arow] = f2tf32(pb[j].x);
            Bs[kh + j * 4 + 1][arow] = f2tf32(pb[j].y);
            Bs[kh + j * 4 + 2][arow] = f2tf32(pb[j].z);
            Bs[kh + j * 4 + 3][arow] = f2tf32(pb[j].w);
        }
        __syncthreads();

        if (kt + 1 < NKT) {            // prefetch next tile into registers
            aptr += BK; bptr += BK;
#pragma unroll
            for (int j = 0; j < 4; j++) {
                pa[j] = *(const float4*)(aptr + j * 4);
                pb[j] = *(const float4*)(bptr + j * 4);
            }
        }

#pragma unroll
        for (int ks = 0; ks < 4; ks++) {
            const int k8 = ks * 8;
            uint32_t af[2][4], bf[4][2];
#pragma unroll
            for (int mf = 0; mf < 2; mf++) {
                const int m = wm + mf * 16 + g;
                af[mf][0] = As[k8 + tig][m];
                af[mf][1] = As[k8 + tig][m + 8];
                af[mf][2] = As[k8 + tig + 4][m];
                af[mf][3] = As[k8 + tig + 4][m + 8];
            }
#pragma unroll
            for (int nf = 0; nf < 4; nf++) {
                const int n = wn + nf * 8 + g;
                bf[nf][0] = Bs[k8 + tig][n];
                bf[nf][1] = Bs[k8 + tig + 4][n];
            }
#pragma unroll
            for (int mf = 0; mf < 2; mf++)
#pragma unroll
                for (int nf = 0; nf < 4; nf++)
                    mma_tf32(acc[mf][nf], af[mf], bf[nf]);
        }
        __syncthreads();
    }

    // epilogue (+ bias for D)
    float2 bv[4];
#pragma unroll
    for (int nf = 0; nf < 4; nf++) {
        if (isE) bv[nf] = make_float2(0.f, 0.f);
        else     bv[nf] = *(const float2*)(bias + col0 + wn + nf * 8 + tig * 2);
    }
#pragma unroll
    for (int mf = 0; mf < 2; mf++) {
        const int r = row0 + wm + mf * 16 + g;
#pragma unroll
        for (int nf = 0; nf < 4; nf++) {
            const int c = col0 + wn + nf * 8 + tig * 2;
            float2 v0 = make_float2(acc[mf][nf][0] + bv[nf].x,
                                    acc[mf][nf][1] + bv[nf].y);
            float2 v1 = make_float2(acc[mf][nf][2] + bv[nf].x,
                                    acc[mf][nf][3] + bv[nf].y);
            *(float2*)(C + (size_t)r * NDIM + c)       = v0;
            *(float2*)(C + (size_t)(r + 8) * NDIM + c) = v1;
        }
    }
}

// ---------------------------------------------------------------------------
// Broadcast add: out[b,t,u,v] = E[b*256+t, v] + D[b*64+u, v]
// TT=1 -> 2048 blocks x 256 threads (~13 CTA/SM): store stream scales with
// resident warps (R6/R7 lesson). u unrolled x4 for D-load MLP.
// ---------------------------------------------------------------------------
__global__ void __launch_bounds__(256)
bcast_add(const float* __restrict__ E, const float* __restrict__ D,
          float* __restrict__ out)
{
    const int tile = blockIdx.x;            // 0..2047
    const int b    = tile >> 8;             // 0..7
    const int t    = tile & 255;
    const int v4   = threadIdx.x;

    const float4* E4 = (const float4*)E;
    const float4* D4 = (const float4*)D;
    float4*       O4 = (float4*)out;

    const float4 e = E4[(size_t)(b * 256 + t) * 256 + v4];

    const size_t base = ((size_t)(b * 256 + t) * 64) * 256 + v4;
    const float4* Dp  = D4 + (size_t)(b * 64) * 256 + v4;

    for (int u = 0; u < 64; u += 4) {
        float4 d0 = __ldg(Dp + (size_t)(u + 0) * 256);
        float4 d1 = __ldg(Dp + (size_t)(u + 1) * 256);
        float4 d2 = __ldg(Dp + (size_t)(u + 2) * 256);
        float4 d3 = __ldg(Dp + (size_t)(u + 3) * 256);

        const size_t o = base + (size_t)u * 256;
        O4[o]           = make_float4(e.x + d0.x, e.y + d0.y, e.z + d0.z, e.w + d0.w);
        O4[o + 256]     = make_float4(e.x + d1.x, e.y + d1.y, e.z + d1.z, e.w + d1.w);
        O4[o + 2 * 256] = make_float4(e.x + d2.x, e.y + d2.y, e.z + d2.z, e.w + d2.w);
        O4[o + 3 * 256] = make_float4(e.x + d3.x, e.y + d3.y, e.z + d3.z, e.w + d3.w);
    }
}

// ---------------------------------------------------------------------------
extern "C" void kernel_launch(void* const* d_in, const int* in_sizes, int n_in,
                              void* d_out, int out_size) {
    const float* enc  = (const float*)d_in[0];  // (8,256,512)
    const float* dec  = (const float*)d_in[1];  // (8,64,512)
    const float* W    = (const float*)d_in[2];  // (1024,512)
    const float* bias = (const float*)d_in[3];  // (1024,)
    float* out = (float*)d_out;                 // (8,256,64,1024)

    float *E, *D;
    cudaGetSymbolAddress((void**)&E, g_E);
    cudaGetSymbolAddress((void**)&D, g_D);

    gemm_tf32<<<dim3(NDIM / BN, 40), 128>>>(enc, dec, W, bias, E, D);
    bcast_add<<<2048, 256>>>(E, D, out);
}

// round 10
// speedup vs baseline: 1.5399x; 1.1268x over previous
#include <cuda_runtime.h>
#include <cuda_fp16.h>
#include <cstdint>
#include <cstddef>

// Scratch: E = enc@W^T (2048x1024), D = dec@W^T + bias (512x1024)
__device__ float g_E[2048 * 1024];
__device__ float g_D[512 * 1024];

constexpr int KDIM = 512, NDIM = 1024;
constexpr int BM = 128, BN = 128, BK = 32;   // BK in floats; 16 half2 k-rows
constexpr int NKT = KDIM / BK;               // 16 k-tiles
constexpr int STR = 136;                     // stride mod 32 == 8 -> frag reads conflict-free

// fp16 mma m16n8k16, fp32 accumulate
__device__ __forceinline__ void mma_f16(float* c, const uint32_t* a, const uint32_t* b) {
    asm volatile(
        "mma.sync.aligned.m16n8k16.row.col.f32.f16.f16.f32 "
        "{%0,%1,%2,%3}, {%4,%5,%6,%7}, {%8,%9}, {%0,%1,%2,%3};\n"
        : "+f"(c[0]), "+f"(c[1]), "+f"(c[2]), "+f"(c[3])
        : "r"(a[0]), "r"(a[1]), "r"(a[2]), "r"(a[3]), "r"(b[0]), "r"(b[1]));
}

__device__ __forceinline__ uint32_t pack_h2(float x, float y) {
    __half2 h = __floats2half2_rn(x, y);
    return *reinterpret_cast<uint32_t*>(&h);
}

// ---------------------------------------------------------------------------
// fp16 tensor-core NT GEMM producing both E and D in one launch.
// grid = (8, 20): y<16 -> E rows (enc), else D rows (dec, +bias).
// Block 128x128, 8 warps (2x4), warp tile 64x32, mma m16n8k16 (fp32 acc).
// Smem: half2 packed along K: As2[k2][m], k2 = k/2, 16 k2-rows per tile.
// ---------------------------------------------------------------------------
__global__ void __launch_bounds__(256)
gemm_f16(const float* __restrict__ enc, const float* __restrict__ dec,
         const float* __restrict__ W, const float* __restrict__ bias,
         float* __restrict__ E, float* __restrict__ D)
{
    __shared__ uint32_t As[BK / 2][STR];   // [k2][m]
    __shared__ uint32_t Bs[BK / 2][STR];   // [k2][n]

    const int tid  = threadIdx.x;
    const int col0 = blockIdx.x * BN;
    const bool isE = (blockIdx.y < 16);
    const int row0 = isE ? blockIdx.y * BM : (blockIdx.y - 16) * BM;
    const float* A = isE ? enc : dec;
    float* C       = isE ? E : D;

    // Staging: 2 threads per row, each covers 16 consecutive k (4 float4)
    const int arow = tid >> 1;
    const int kh   = (tid & 1) * 16;       // float offset
    const int k2h  = (tid & 1) * 8;        // half2-row offset
    const float* aptr = A + (size_t)(row0 + arow) * KDIM + kh;
    const float* bptr = W + (size_t)(col0 + arow) * KDIM + kh;

    const int lane = tid & 31, warp = tid >> 5;
    const int g = lane >> 2, tig = lane & 3;
    const int wm = (warp >> 2) * 64, wn = (warp & 3) * 32;

    float acc[4][4][4];
#pragma unroll
    for (int mf = 0; mf < 4; mf++)
#pragma unroll
        for (int nf = 0; nf < 4; nf++)
#pragma unroll
            for (int i = 0; i < 4; i++) acc[mf][nf][i] = 0.f;

    float4 pa[4], pb[4];
#pragma unroll
    for (int j = 0; j < 4; j++) {
        pa[j] = *(const float4*)(aptr + j * 4);
        pb[j] = *(const float4*)(bptr + j * 4);
    }

    for (int kt = 0; kt < NKT; kt++) {
        // stage prefetched tile: each float4 -> two half2 at k2 = k2h+2j, +1
#pragma unroll
        for (int j = 0; j < 4; j++) {
            As[k2h + j * 2 + 0][arow] = pack_h2(pa[j].x, pa[j].y);
            As[k2h + j * 2 + 1][arow] = pack_h2(pa[j].z, pa[j].w);
            Bs[k2h + j * 2 + 0][arow] = pack_h2(pb[j].x, pb[j].y);
            Bs[k2h + j * 2 + 1][arow] = pack_h2(pb[j].z, pb[j].w);
        }
        __syncthreads();

        if (kt + 1 < NKT) {                // prefetch next tile
            aptr += BK; bptr += BK;
#pragma unroll
            for (int j = 0; j < 4; j++) {
                pa[j] = *(const float4*)(aptr + j * 4);
                pb[j] = *(const float4*)(bptr + j * 4);
            }
        }

        // 2 k16-steps per tile (k2 groups of 8)
#pragma unroll
        for (int ks = 0; ks < 2; ks++) {
            const int k8 = ks * 8;
            uint32_t af[4][4], bf[4][2];
#pragma unroll
            for (int mf = 0; mf < 4; mf++) {
                const int m = wm + mf * 16 + g;
                af[mf][0] = As[k8 + tig][m];        // (k2=tig,   row m)
                af[mf][1] = As[k8 + tig][m + 8];    // (k2=tig,   row m+8)
                af[mf][2] = As[k8 + tig + 4][m];    // (k2=tig+4, row m)
                af[mf][3] = As[k8 + tig + 4][m + 8];
            }
#pragma unroll
            for (int nf = 0; nf < 4; nf++) {
                const int n = wn + nf * 8 + g;
                bf[nf][0] = Bs[k8 + tig][n];
                bf[nf][1] = Bs[k8 + tig + 4][n];
            }
#pragma unroll
            for (int mf = 0; mf < 4; mf++)
#pragma unroll
                for (int nf = 0; nf < 4; nf++)
                    mma_f16(acc[mf][nf], af[mf], bf[nf]);
        }
        __syncthreads();
    }

    // epilogue (+ bias for D)
    float2 bv[4];
#pragma unroll
    for (int nf = 0; nf < 4; nf++) {
        if (isE) bv[nf] = make_float2(0.f, 0.f);
        else     bv[nf] = *(const float2*)(bias + col0 + wn + nf * 8 + tig * 2);
    }
#pragma unroll
    for (int mf = 0; mf < 4; mf++) {
        const int r = row0 + wm + mf * 16 + g;
#pragma unroll
        for (int nf = 0; nf < 4; nf++) {
            const int c = col0 + wn + nf * 8 + tig * 2;
            float2 v0 = make_float2(acc[mf][nf][0] + bv[nf].x,
                                    acc[mf][nf][1] + bv[nf].y);
            float2 v1 = make_float2(acc[mf][nf][2] + bv[nf].x,
                                    acc[mf][nf][3] + bv[nf].y);
            *(float2*)(C + (size_t)r * NDIM + c)       = v0;
            *(float2*)(C + (size_t)(r + 8) * NDIM + c) = v1;
        }
    }
}

// ---------------------------------------------------------------------------
// Broadcast add (R8, measured 87.8us / 70% DRAM): unchanged.
// out[b,t,u,v] = E[b*256+t, v] + D[b*64+u, v]
// ---------------------------------------------------------------------------
__global__ void __launch_bounds__(256)
bcast_add(const float* __restrict__ E, const float* __restrict__ D,
          float* __restrict__ out)
{
    const int tile = blockIdx.x;            // 0..2047
    const int b    = tile >> 8;
    const int t    = tile & 255;
    const int v4   = threadIdx.x;

    const float4* E4 = (const float4*)E;
    const float4* D4 = (const float4*)D;
    float4*       O4 = (float4*)out;

    const float4 e = E4[(size_t)(b * 256 + t) * 256 + v4];
    const size_t base = ((size_t)(b * 256 + t) * 64) * 256 + v4;
    const float4* Dp  = D4 + (size_t)(b * 64) * 256 + v4;

    for (int u = 0; u < 64; u += 4) {
        float4 d0 = __ldg(Dp + (size_t)(u + 0) * 256);
        float4 d1 = __ldg(Dp + (size_t)(u + 1) * 256);
        float4 d2 = __ldg(Dp + (size_t)(u + 2) * 256);
        float4 d3 = __ldg(Dp + (size_t)(u + 3) * 256);

        const size_t o = base + (size_t)u * 256;
        O4[o]           = make_float4(e.x + d0.x, e.y + d0.y, e.z + d0.z, e.w + d0.w);
        O4[o + 256]     = make_float4(e.x + d1.x, e.y + d1.y, e.z + d1.z, e.w + d1.w);
        O4[o + 2 * 256] = make_float4(e.x + d2.x, e.y + d2.y, e.z + d2.z, e.w + d2.w);
        O4[o + 3 * 256] = make_float4(e.x + d3.x, e.y + d3.y, e.z + d3.z, e.w + d3.w);
    }
}

// ---------------------------------------------------------------------------
extern "C" void kernel_launch(void* const* d_in, const int* in_sizes, int n_in,
                              void* d_out, int out_size) {
    const float* enc  = (const float*)d_in[0];  // (8,256,512)
    const float* dec  = (const float*)d_in[1];  // (8,64,512)
    const float* W    = (const float*)d_in[2];  // (1024,512)
    const float* bias = (const float*)d_in[3];  // (1024,)
    float* out = (float*)d_out;                 // (8,256,64,1024)

    float *E, *D;
    cudaGetSymbolAddress((void**)&E, g_E);
    cudaGetSymbolAddress((void**)&D, g_D);

    gemm_f16<<<dim3(NDIM / BN, 20), 256>>>(enc, dec, W, bias, E, D);
    bcast_add<<<2048, 256>>>(E, D, out);
}